// round 1
// baseline (speedup 1.0000x reference)
#include <cuda_runtime.h>

#define BSZ 8
#define SEQ 4096
#define NH 32
#define HD 128
#define QLR 1536
#define NQ (NH*HD)      // 4096
#define KVROW (NH*256)  // floats per (b,s) row = 8192

// Scratch for projected q (allowed: __device__ global, no allocation)
__device__ __align__(16) float g_q[BSZ * NQ];

// ---------------------------------------------------------------------------
// Kernel 1: q = hidden_states_q @ W_q + b_q      (8 x 1536) @ (1536 x 4096)
// 128 blocks x 256 threads. Block owns 32 output columns; threads split the
// reduction dim 8 ways (192 r each), combine via smem. W_q read exactly once.
// ---------------------------------------------------------------------------
__global__ __launch_bounds__(256) void qproj_kernel(const float* __restrict__ hs,
                                                    const float* __restrict__ W,
                                                    const float* __restrict__ bq)
{
    __shared__ float part[8][BSZ][32];   // [r-group][b][col] = 8 KB

    const int tid = threadIdx.x;
    const int d   = tid & 31;            // column within the block's 32-chunk
    const int g   = tid >> 5;            // r-group 0..7
    const int n   = blockIdx.x * 32 + d; // global output column

    float acc[BSZ];
#pragma unroll
    for (int b = 0; b < BSZ; ++b) acc[b] = 0.f;

    const int r0 = g * (QLR / 8);        // 192 r per group
#pragma unroll 4
    for (int rr = 0; rr < QLR / 8; ++rr) {
        const int r = r0 + rr;
        const float w = __ldg(&W[(size_t)r * NQ + n]);
#pragma unroll
        for (int b = 0; b < BSZ; ++b)
            acc[b] += __ldg(&hs[b * QLR + r]) * w;
    }

#pragma unroll
    for (int b = 0; b < BSZ; ++b) part[g][b][d] = acc[b];
    __syncthreads();

    // reuse g as batch index for the write phase: 8 b x 32 d = 256 threads
    {
        const int b = g;
        float v = 0.f;
#pragma unroll
        for (int gg = 0; gg < 8; ++gg) v += part[gg][b][d];
        g_q[b * NQ + n] = v + __ldg(&bq[n]);
    }
}

// ---------------------------------------------------------------------------
// Kernel 2: attention. One CTA per (b, h); 256 threads (8 warps).
// Pass 1: scores -> smem (warp per s, lane-float4 dot + shfl reduce).
// Softmax stats in smem. Pass 2: warp per s, lane owns 4 dims.
// ---------------------------------------------------------------------------
__global__ __launch_bounds__(256) void attn_kernel(const float* __restrict__ kv,
                                                   float* __restrict__ out)
{
    __shared__ float  sc[SEQ];           // 16 KB unnormalized scores/probs
    __shared__ float4 part[8][32];       // 4 KB per-warp output partials
    __shared__ float  red[8];            // warp reduction scratch

    const int b    = blockIdx.x >> 5;
    const int h    = blockIdx.x & 31;
    const int tid  = threadIdx.x;
    const int w    = tid >> 5;
    const int lane = tid & 31;

    // q vector for this head: lane holds dims [4*lane, 4*lane+4)
    const float4 qv = *(const float4*)(&g_q[b * NQ + h * HD + 4 * lane]);

    // base of (b, s=0, h, c=0); s stride = KVROW floats
    const float* kvb = kv + ((size_t)b * SEQ * NH + h) * 256;

    // ---------------- Pass 1: scores ----------------
    for (int i = 0; i < SEQ / 32; ++i) {           // 128 iters, 4 s per warp
        float dsum[4];
#pragma unroll
        for (int j = 0; j < 4; ++j) {
            const int s = w + 8 * j + 32 * i;
            const float4 k = *(const float4*)(kvb + (size_t)s * KVROW + 4 * lane);
            dsum[j] = k.x * qv.x + k.y * qv.y + k.z * qv.z + k.w * qv.w;
        }
#pragma unroll
        for (int j = 0; j < 4; ++j) {
            float v = dsum[j];
            v += __shfl_xor_sync(0xffffffffu, v, 16);
            v += __shfl_xor_sync(0xffffffffu, v, 8);
            v += __shfl_xor_sync(0xffffffffu, v, 4);
            v += __shfl_xor_sync(0xffffffffu, v, 2);
            v += __shfl_xor_sync(0xffffffffu, v, 1);
            if (lane == 0) sc[w + 8 * j + 32 * i] = v;
        }
    }
    __syncthreads();

    // ---------------- Softmax stats ----------------
    float m = -1e30f;
#pragma unroll
    for (int k = 0; k < SEQ / 256; ++k)
        m = fmaxf(m, sc[tid + 256 * k]);
    m = fmaxf(m, __shfl_xor_sync(0xffffffffu, m, 16));
    m = fmaxf(m, __shfl_xor_sync(0xffffffffu, m, 8));
    m = fmaxf(m, __shfl_xor_sync(0xffffffffu, m, 4));
    m = fmaxf(m, __shfl_xor_sync(0xffffffffu, m, 2));
    m = fmaxf(m, __shfl_xor_sync(0xffffffffu, m, 1));
    if (lane == 0) red[w] = m;
    __syncthreads();

    float gmax = red[0];
#pragma unroll
    for (int ww = 1; ww < 8; ++ww) gmax = fmaxf(gmax, red[ww]);

    float lsum = 0.f;
#pragma unroll
    for (int k = 0; k < SEQ / 256; ++k) {
        const float e = __expf(sc[tid + 256 * k] - gmax);
        sc[tid + 256 * k] = e;
        lsum += e;
    }
    lsum += __shfl_xor_sync(0xffffffffu, lsum, 16);
    lsum += __shfl_xor_sync(0xffffffffu, lsum, 8);
    lsum += __shfl_xor_sync(0xffffffffu, lsum, 4);
    lsum += __shfl_xor_sync(0xffffffffu, lsum, 2);
    lsum += __shfl_xor_sync(0xffffffffu, lsum, 1);
    __syncthreads();                 // everyone done reading red (gmax)
    if (lane == 0) red[w] = lsum;
    __syncthreads();

    float total = red[0];
#pragma unroll
    for (int ww = 1; ww < 8; ++ww) total += red[ww];
    const float inv = 1.f / total;

    // ---------------- Pass 2: output ----------------
    float4 acc = make_float4(0.f, 0.f, 0.f, 0.f);
    const float* vb = kvb + 128;     // value half of the row
    for (int i = 0; i < SEQ / 32; ++i) {           // 4 s per warp per iter
#pragma unroll
        for (int j = 0; j < 4; ++j) {
            const int s = w + 8 * j + 32 * i;
            const float  p = sc[s];
            const float4 v = *(const float4*)(vb + (size_t)s * KVROW + 4 * lane);
            acc.x += p * v.x;
            acc.y += p * v.y;
            acc.z += p * v.z;
            acc.w += p * v.w;
        }
    }
    part[w][lane] = acc;
    __syncthreads();

    if (tid < 32) {
        float4 r = part[0][tid];
#pragma unroll
        for (int ww = 1; ww < 8; ++ww) {
            const float4 t = part[ww][tid];
            r.x += t.x; r.y += t.y; r.z += t.z; r.w += t.w;
        }
        r.x *= inv; r.y *= inv; r.z *= inv; r.w *= inv;
        *(float4*)(&out[((size_t)b * NH + h) * HD + 4 * tid]) = r;
    }
}

// ---------------------------------------------------------------------------
extern "C" void kernel_launch(void* const* d_in, const int* in_sizes, int n_in,
                              void* d_out, int out_size)
{
    const float* hs = (const float*)d_in[0];  // (8, 1536)
    const float* kv = (const float*)d_in[1];  // (8, 4096, 32, 256)
    const float* W  = (const float*)d_in[2];  // (1536, 4096)
    const float* bq = (const float*)d_in[3];  // (4096,)
    float* out = (float*)d_out;               // (8, 4096)

    qproj_kernel<<<NQ / 32, 256>>>(hs, W, bq);
    attn_kernel<<<BSZ * NH, 256>>>(kv, out);
}

// round 2
// speedup vs baseline: 1.6171x; 1.6171x over previous
#include <cuda_runtime.h>

#define BSZ 8
#define SEQ 4096
#define NH 32
#define HD 128
#define QLR 1536
#define NQ (NH*HD)      // 4096
#define KVROW (NH*256)  // floats per (b,s) row = 8192
#define NCHUNK 2
#define CHUNK (SEQ/NCHUNK)   // 2048

// Device-global scratch (no allocation allowed)
__device__ __align__(16) float g_q[BSZ * NQ];
__device__ __align__(16) float g_po[BSZ * NH * NCHUNK * HD];  // unnormalized partial outputs
__device__ float g_pm[BSZ * NH * NCHUNK];                     // partial max
__device__ float g_ps[BSZ * NH * NCHUNK];                     // partial expsum

// ---------------------------------------------------------------------------
// Kernel 1: q = hs @ W + b.  128 blocks x 256 threads.
// Block owns 32 cols (8 float4 quads). Threads = 8 quads x 32 r-groups (48 r).
// float4 W loads -> 4x the bytes per scoreboard slot vs round-1 scalar loads.
// ---------------------------------------------------------------------------
__global__ __launch_bounds__(256) void qproj_kernel(const float* __restrict__ hs,
                                                    const float* __restrict__ W,
                                                    const float* __restrict__ bq)
{
    __shared__ float part[32][BSZ][33];   // [g][b][col+pad] = 33.8 KB

    const int tid = threadIdx.x;
    const int q   = tid & 7;              // quad 0..7
    const int g   = tid >> 3;             // r-group 0..31
    const int n4  = blockIdx.x * 32 + q * 4;

    float4 acc[BSZ];
#pragma unroll
    for (int b = 0; b < BSZ; ++b) acc[b] = make_float4(0.f, 0.f, 0.f, 0.f);

    const int r0 = g * (QLR / 32);        // 48 r per group
#pragma unroll 4
    for (int rr = 0; rr < QLR / 32; ++rr) {
        const int r = r0 + rr;
        const float4 w4 = *(const float4*)(&W[(size_t)r * NQ + n4]);
#pragma unroll
        for (int b = 0; b < BSZ; ++b) {
            const float hb = __ldg(&hs[b * QLR + r]);
            acc[b].x += hb * w4.x;
            acc[b].y += hb * w4.y;
            acc[b].z += hb * w4.z;
            acc[b].w += hb * w4.w;
        }
    }

#pragma unroll
    for (int b = 0; b < BSZ; ++b) {
        part[g][b][q * 4 + 0] = acc[b].x;
        part[g][b][q * 4 + 1] = acc[b].y;
        part[g][b][q * 4 + 2] = acc[b].z;
        part[g][b][q * 4 + 3] = acc[b].w;
    }
    __syncthreads();

    // 256 outputs: thread -> (b, col)
    {
        const int b   = tid >> 5;
        const int col = tid & 31;
        float v = 0.f;
#pragma unroll
        for (int gg = 0; gg < 32; ++gg) v += part[gg][b][col];
        const int n = blockIdx.x * 32 + col;
        g_q[b * NQ + n] = v + __ldg(&bq[n]);
    }
}

// ---------------------------------------------------------------------------
// Kernel 2: split-KV attention. grid = BSZ*NH*NCHUNK = 512 CTAs, 256 thr.
// Each CTA: scores for its 2048-s chunk -> smem, local softmax stats,
// unnormalized weighted-V partial -> scratch. Single balanced wave.
// ---------------------------------------------------------------------------
__global__ __launch_bounds__(256) void attn_kernel(const float* __restrict__ kv)
{
    __shared__ float  sc[CHUNK];          // 8 KB
    __shared__ float4 part[8][32];        // 4 KB
    __shared__ float  red[8];

    const int id   = blockIdx.x;          // (b*NH + h)*NCHUNK + c
    const int c    = id & (NCHUNK - 1);
    const int bh   = id >> 1;
    const int b    = bh >> 5;
    const int h    = bh & 31;
    const int tid  = threadIdx.x;
    const int w    = tid >> 5;
    const int lane = tid & 31;

    const float4 qv = *(const float4*)(&g_q[b * NQ + h * HD + 4 * lane]);
    const float* kvb = kv + ((size_t)(b * SEQ + c * CHUNK) * NH + h) * 256;

    // ---------------- Pass 1: scores (9-shuffle 4-way butterfly) ----------
    for (int i = 0; i < CHUNK / 32; ++i) {            // 64 iters, 4 s per warp
        float d0, d1, d2, d3;
        {
            const float4 k0 = *(const float4*)(kvb + (size_t)(w +  0 + 32*i) * KVROW + 4*lane);
            const float4 k1 = *(const float4*)(kvb + (size_t)(w +  8 + 32*i) * KVROW + 4*lane);
            const float4 k2 = *(const float4*)(kvb + (size_t)(w + 16 + 32*i) * KVROW + 4*lane);
            const float4 k3 = *(const float4*)(kvb + (size_t)(w + 24 + 32*i) * KVROW + 4*lane);
            d0 = k0.x*qv.x + k0.y*qv.y + k0.z*qv.z + k0.w*qv.w;
            d1 = k1.x*qv.x + k1.y*qv.y + k1.z*qv.z + k1.w*qv.w;
            d2 = k2.x*qv.x + k2.y*qv.y + k2.z*qv.z + k2.w*qv.w;
            d3 = k3.x*qv.x + k3.y*qv.y + k3.z*qv.z + k3.w*qv.w;
        }
        // stage A: xor16 on each value
        const float a0 = d0 + __shfl_xor_sync(0xffffffffu, d0, 16);
        const float a1 = d1 + __shfl_xor_sync(0xffffffffu, d1, 16);
        const float a2 = d2 + __shfl_xor_sync(0xffffffffu, d2, 16);
        const float a3 = d3 + __shfl_xor_sync(0xffffffffu, d3, 16);
        // merge by lane bit 16
        float m0 = (lane & 16) ? a1 : a0;
        float m1 = (lane & 16) ? a3 : a2;
        // stage B: xor8
        m0 += __shfl_xor_sync(0xffffffffu, m0, 8);
        m1 += __shfl_xor_sync(0xffffffffu, m1, 8);
        // merge by lane bit 8
        float n = (lane & 8) ? m1 : m0;
        // stage C: xor4,2,1
        n += __shfl_xor_sync(0xffffffffu, n, 4);
        n += __shfl_xor_sync(0xffffffffu, n, 2);
        n += __shfl_xor_sync(0xffffffffu, n, 1);
        // lane0->d0, lane8->d2, lane16->d1, lane24->d3
        if ((lane & 7) == 0) {
            const int j = ((lane >> 4) & 1) | (((lane >> 3) & 1) << 1);
            sc[w + 8 * j + 32 * i] = n;
        }
    }
    __syncthreads();

    // ---------------- Local softmax stats ----------------
    float m = -1e30f;
#pragma unroll
    for (int k = 0; k < CHUNK / 256; ++k)
        m = fmaxf(m, sc[tid + 256 * k]);
    m = fmaxf(m, __shfl_xor_sync(0xffffffffu, m, 16));
    m = fmaxf(m, __shfl_xor_sync(0xffffffffu, m, 8));
    m = fmaxf(m, __shfl_xor_sync(0xffffffffu, m, 4));
    m = fmaxf(m, __shfl_xor_sync(0xffffffffu, m, 2));
    m = fmaxf(m, __shfl_xor_sync(0xffffffffu, m, 1));
    if (lane == 0) red[w] = m;
    __syncthreads();

    float gmax = red[0];
#pragma unroll
    for (int ww = 1; ww < 8; ++ww) gmax = fmaxf(gmax, red[ww]);

    float lsum = 0.f;
#pragma unroll
    for (int k = 0; k < CHUNK / 256; ++k) {
        const float e = __expf(sc[tid + 256 * k] - gmax);
        sc[tid + 256 * k] = e;
        lsum += e;
    }
    lsum += __shfl_xor_sync(0xffffffffu, lsum, 16);
    lsum += __shfl_xor_sync(0xffffffffu, lsum, 8);
    lsum += __shfl_xor_sync(0xffffffffu, lsum, 4);
    lsum += __shfl_xor_sync(0xffffffffu, lsum, 2);
    lsum += __shfl_xor_sync(0xffffffffu, lsum, 1);
    __syncthreads();                  // done reading red (gmax)
    if (lane == 0) red[w] = lsum;
    __syncthreads();

    float total = red[0];
#pragma unroll
    for (int ww = 1; ww < 8; ++ww) total += red[ww];

    // ---------------- Pass 2: unnormalized output ----------------
    float4 acc0 = make_float4(0.f, 0.f, 0.f, 0.f);
    float4 acc1 = make_float4(0.f, 0.f, 0.f, 0.f);
    const float* vb = kvb + 128;
    for (int i = 0; i < CHUNK / 32; ++i) {
        {
            const int s = w + 32 * i;
            const float  p = sc[s];
            const float4 v = *(const float4*)(vb + (size_t)s * KVROW + 4 * lane);
            acc0.x += p * v.x; acc0.y += p * v.y; acc0.z += p * v.z; acc0.w += p * v.w;
        }
        {
            const int s = w + 8 + 32 * i;
            const float  p = sc[s];
            const float4 v = *(const float4*)(vb + (size_t)s * KVROW + 4 * lane);
            acc1.x += p * v.x; acc1.y += p * v.y; acc1.z += p * v.z; acc1.w += p * v.w;
        }
        {
            const int s = w + 16 + 32 * i;
            const float  p = sc[s];
            const float4 v = *(const float4*)(vb + (size_t)s * KVROW + 4 * lane);
            acc0.x += p * v.x; acc0.y += p * v.y; acc0.z += p * v.z; acc0.w += p * v.w;
        }
        {
            const int s = w + 24 + 32 * i;
            const float  p = sc[s];
            const float4 v = *(const float4*)(vb + (size_t)s * KVROW + 4 * lane);
            acc1.x += p * v.x; acc1.y += p * v.y; acc1.z += p * v.z; acc1.w += p * v.w;
        }
    }
    acc0.x += acc1.x; acc0.y += acc1.y; acc0.z += acc1.z; acc0.w += acc1.w;
    part[w][lane] = acc0;
    __syncthreads();

    if (tid < 32) {
        float4 r = part[0][tid];
#pragma unroll
        for (int ww = 1; ww < 8; ++ww) {
            const float4 t = part[ww][tid];
            r.x += t.x; r.y += t.y; r.z += t.z; r.w += t.w;
        }
        *(float4*)(&g_po[(size_t)id * HD + 4 * tid]) = r;   // unnormalized
        if (tid == 0) { g_pm[id] = gmax; g_ps[id] = total; }
    }
}

// ---------------------------------------------------------------------------
// Kernel 3: combine the NCHUNK partials. 256 blocks x 128 threads.
// ---------------------------------------------------------------------------
__global__ __launch_bounds__(128) void combine_kernel(float* __restrict__ out)
{
    const int bh = blockIdx.x;            // b*NH + h
    const int d  = threadIdx.x;
    const int i0 = bh * NCHUNK;
    const int i1 = i0 + 1;

    const float m0 = g_pm[i0], m1 = g_pm[i1];
    const float gm = fmaxf(m0, m1);
    const float e0 = __expf(m0 - gm);
    const float e1 = __expf(m1 - gm);
    const float inv = 1.f / (e0 * g_ps[i0] + e1 * g_ps[i1]);

    out[(size_t)bh * HD + d] =
        (e0 * g_po[(size_t)i0 * HD + d] + e1 * g_po[(size_t)i1 * HD + d]) * inv;
}

// ---------------------------------------------------------------------------
extern "C" void kernel_launch(void* const* d_in, const int* in_sizes, int n_in,
                              void* d_out, int out_size)
{
    const float* hs = (const float*)d_in[0];  // (8, 1536)
    const float* kv = (const float*)d_in[1];  // (8, 4096, 32, 256)
    const float* W  = (const float*)d_in[2];  // (1536, 4096)
    const float* bq = (const float*)d_in[3];  // (4096,)
    float* out = (float*)d_out;               // (8, 4096)

    qproj_kernel<<<NQ / 32, 256>>>(hs, W, bq);
    attn_kernel<<<BSZ * NH * NCHUNK, 256>>>(kv);
    combine_kernel<<<BSZ * NH, 128>>>(out);
}

// round 4
// speedup vs baseline: 1.6550x; 1.0235x over previous
#include <cuda_runtime.h>

#define BSZ 8
#define SEQ 4096
#define NH 32
#define HD 128
#define QLR 1536
#define NQ (NH*HD)      // 4096
#define KVROW (NH*256)  // floats per (b,s) row = 8192
#define NCHUNK 4
#define CHUNK (SEQ/NCHUNK)   // 1024

#define RB 16            // r-split blocks for qproj
#define CB 32            // col blocks (128 cols each)
#define RPB (QLR/RB)     // 96 rows per block
#define RPW (RPB/8)      // 12 rows per warp

// Device-global scratch (no allocation allowed)
__device__ __align__(16) float g_q[BSZ * NQ];
__device__ __align__(16) float g_qpart[RB * BSZ * NQ];        // 2 MB split-K partials
__device__ __align__(16) float g_po[BSZ * NH * NCHUNK * HD];  // unnormalized partial outputs
__device__ float g_pm[BSZ * NH * NCHUNK];                     // partial max
__device__ float g_ps[BSZ * NH * NCHUNK];                     // partial expsum

// ---------------------------------------------------------------------------
// qproj stage 1: split-K partial GEMM. grid = CB*RB = 512 CTAs x 256 thr.
// Block = (128 cols, 96 rows). Warp streams 12 coalesced 512B row segments;
// 12 independent float4 LDGs in flight per thread.
// ---------------------------------------------------------------------------
__global__ __launch_bounds__(256) void qproj1_kernel(const float* __restrict__ hs,
                                                     const float* __restrict__ W)
{
    __shared__ float4 part[8][32][BSZ];   // 32 KB

    const int cb   = blockIdx.x & (CB - 1);
    const int rb   = blockIdx.x >> 5;
    const int tid  = threadIdx.x;
    const int w    = tid >> 5;
    const int lane = tid & 31;

    const int n4 = cb * 128 + lane * 4;
    const int r0 = rb * RPB + w * RPW;

    float4 acc[BSZ];
#pragma unroll
    for (int b = 0; b < BSZ; ++b) acc[b] = make_float4(0.f, 0.f, 0.f, 0.f);

#pragma unroll
    for (int rr = 0; rr < RPW; ++rr) {
        const int r = r0 + rr;
        const float4 w4 = *(const float4*)(&W[(size_t)r * NQ + n4]);
#pragma unroll
        for (int b = 0; b < BSZ; ++b) {
            const float hb = __ldg(&hs[b * QLR + r]);
            acc[b].x += hb * w4.x;
            acc[b].y += hb * w4.y;
            acc[b].z += hb * w4.z;
            acc[b].w += hb * w4.w;
        }
    }

#pragma unroll
    for (int b = 0; b < BSZ; ++b) part[w][lane][b] = acc[b];
    __syncthreads();

    // 256 threads -> (b, lane) pairs; sum 8 warp partials, store float4
    {
        const int b2 = tid >> 5;
        const int l2 = tid & 31;
        float4 s = part[0][l2][b2];
#pragma unroll
        for (int ww = 1; ww < 8; ++ww) {
            const float4 t = part[ww][l2][b2];
            s.x += t.x; s.y += t.y; s.z += t.z; s.w += t.w;
        }
        const int n = cb * 128 + l2 * 4;
        *(float4*)(&g_qpart[((size_t)rb * BSZ + b2) * NQ + n]) = s;
    }
}

// ---------------------------------------------------------------------------
// qproj stage 2: reduce RB partials + bias. 32 blocks x 256 threads (float4).
// ---------------------------------------------------------------------------
__global__ __launch_bounds__(256) void qproj2_kernel(const float* __restrict__ bq)
{
    const int i  = blockIdx.x * 256 + threadIdx.x;   // float4 index into [BSZ][NQ]
    const int b  = i / (NQ / 4);
    const int n  = (i - b * (NQ / 4)) * 4;

    float4 s = *(const float4*)(&bq[n]);
#pragma unroll
    for (int rb = 0; rb < RB; ++rb) {
        const float4 t = *(const float4*)(&g_qpart[((size_t)rb * BSZ + b) * NQ + n]);
        s.x += t.x; s.y += t.y; s.z += t.z; s.w += t.w;
    }
    *(float4*)(&g_q[(size_t)b * NQ + n]) = s;
}

// ---------------------------------------------------------------------------
// attention: split-KV. grid = BSZ*NH*NCHUNK = 1024 CTAs, 256 thr.
// ---------------------------------------------------------------------------
__global__ __launch_bounds__(256) void attn_kernel(const float* __restrict__ kv)
{
    __shared__ float  sc[CHUNK];          // 4 KB
    __shared__ float4 part[8][32];        // 4 KB
    __shared__ float  red[8];

    const int id   = blockIdx.x;          // (b*NH + h)*NCHUNK + c
    const int c    = id & (NCHUNK - 1);
    const int bh   = id / NCHUNK;
    const int b    = bh >> 5;
    const int h    = bh & 31;
    const int tid  = threadIdx.x;
    const int w    = tid >> 5;
    const int lane = tid & 31;

    const float4 qv = *(const float4*)(&g_q[b * NQ + h * HD + 4 * lane]);
    const float* kvb = kv + ((size_t)(b * SEQ + c * CHUNK) * NH + h) * 256;

    // ---------------- Pass 1: scores ----------------
#pragma unroll 2
    for (int i = 0; i < CHUNK / 32; ++i) {            // 32 iters, 4 s per warp
        float d0, d1, d2, d3;
        {
            const float4 k0 = *(const float4*)(kvb + (size_t)(w +  0 + 32*i) * KVROW + 4*lane);
            const float4 k1 = *(const float4*)(kvb + (size_t)(w +  8 + 32*i) * KVROW + 4*lane);
            const float4 k2 = *(const float4*)(kvb + (size_t)(w + 16 + 32*i) * KVROW + 4*lane);
            const float4 k3 = *(const float4*)(kvb + (size_t)(w + 24 + 32*i) * KVROW + 4*lane);
            d0 = k0.x*qv.x + k0.y*qv.y + k0.z*qv.z + k0.w*qv.w;
            d1 = k1.x*qv.x + k1.y*qv.y + k1.z*qv.z + k1.w*qv.w;
            d2 = k2.x*qv.x + k2.y*qv.y + k2.z*qv.z + k2.w*qv.w;
            d3 = k3.x*qv.x + k3.y*qv.y + k3.z*qv.z + k3.w*qv.w;
        }
        const float a0 = d0 + __shfl_xor_sync(0xffffffffu, d0, 16);
        const float a1 = d1 + __shfl_xor_sync(0xffffffffu, d1, 16);
        const float a2 = d2 + __shfl_xor_sync(0xffffffffu, d2, 16);
        const float a3 = d3 + __shfl_xor_sync(0xffffffffu, d3, 16);
        float m0 = (lane & 16) ? a1 : a0;
        float m1 = (lane & 16) ? a3 : a2;
        m0 += __shfl_xor_sync(0xffffffffu, m0, 8);
        m1 += __shfl_xor_sync(0xffffffffu, m1, 8);
        float n = (lane & 8) ? m1 : m0;
        n += __shfl_xor_sync(0xffffffffu, n, 4);
        n += __shfl_xor_sync(0xffffffffu, n, 2);
        n += __shfl_xor_sync(0xffffffffu, n, 1);
        if ((lane & 7) == 0) {
            const int j = ((lane >> 4) & 1) | (((lane >> 3) & 1) << 1);
            sc[w + 8 * j + 32 * i] = n;
        }
    }
    __syncthreads();

    // ---------------- Local softmax stats ----------------
    float m = -1e30f;
#pragma unroll
    for (int k = 0; k < CHUNK / 256; ++k)
        m = fmaxf(m, sc[tid + 256 * k]);
    m = fmaxf(m, __shfl_xor_sync(0xffffffffu, m, 16));
    m = fmaxf(m, __shfl_xor_sync(0xffffffffu, m, 8));
    m = fmaxf(m, __shfl_xor_sync(0xffffffffu, m, 4));
    m = fmaxf(m, __shfl_xor_sync(0xffffffffu, m, 2));
    m = fmaxf(m, __shfl_xor_sync(0xffffffffu, m, 1));
    if (lane == 0) red[w] = m;
    __syncthreads();

    float gmax = red[0];
#pragma unroll
    for (int ww = 1; ww < 8; ++ww) gmax = fmaxf(gmax, red[ww]);

    float lsum = 0.f;
#pragma unroll
    for (int k = 0; k < CHUNK / 256; ++k) {
        const float e = __expf(sc[tid + 256 * k] - gmax);
        sc[tid + 256 * k] = e;
        lsum += e;
    }
    lsum += __shfl_xor_sync(0xffffffffu, lsum, 16);
    lsum += __shfl_xor_sync(0xffffffffu, lsum, 8);
    lsum += __shfl_xor_sync(0xffffffffu, lsum, 4);
    lsum += __shfl_xor_sync(0xffffffffu, lsum, 2);
    lsum += __shfl_xor_sync(0xffffffffu, lsum, 1);
    __syncthreads();                  // done reading red (gmax)
    if (lane == 0) red[w] = lsum;
    __syncthreads();

    float total = red[0];
#pragma unroll
    for (int ww = 1; ww < 8; ++ww) total += red[ww];

    // ---------------- Pass 2: unnormalized output ----------------
    float4 acc0 = make_float4(0.f, 0.f, 0.f, 0.f);
    float4 acc1 = make_float4(0.f, 0.f, 0.f, 0.f);
    const float* vb = kvb + 128;
#pragma unroll 2
    for (int i = 0; i < CHUNK / 32; ++i) {
        {
            const int s = w + 32 * i;
            const float  p = sc[s];
            const float4 v = *(const float4*)(vb + (size_t)s * KVROW + 4 * lane);
            acc0.x += p * v.x; acc0.y += p * v.y; acc0.z += p * v.z; acc0.w += p * v.w;
        }
        {
            const int s = w + 8 + 32 * i;
            const float  p = sc[s];
            const float4 v = *(const float4*)(vb + (size_t)s * KVROW + 4 * lane);
            acc1.x += p * v.x; acc1.y += p * v.y; acc1.z += p * v.z; acc1.w += p * v.w;
        }
        {
            const int s = w + 16 + 32 * i;
            const float  p = sc[s];
            const float4 v = *(const float4*)(vb + (size_t)s * KVROW + 4 * lane);
            acc0.x += p * v.x; acc0.y += p * v.y; acc0.z += p * v.z; acc0.w += p * v.w;
        }
        {
            const int s = w + 24 + 32 * i;
            const float  p = sc[s];
            const float4 v = *(const float4*)(vb + (size_t)s * KVROW + 4 * lane);
            acc1.x += p * v.x; acc1.y += p * v.y; acc1.z += p * v.z; acc1.w += p * v.w;
        }
    }
    acc0.x += acc1.x; acc0.y += acc1.y; acc0.z += acc1.z; acc0.w += acc1.w;
    part[w][lane] = acc0;
    __syncthreads();

    if (tid < 32) {
        float4 r = part[0][tid];
#pragma unroll
        for (int ww = 1; ww < 8; ++ww) {
            const float4 t = part[ww][tid];
            r.x += t.x; r.y += t.y; r.z += t.z; r.w += t.w;
        }
        *(float4*)(&g_po[(size_t)id * HD + 4 * tid]) = r;   // unnormalized
        if (tid == 0) { g_pm[id] = gmax; g_ps[id] = total; }
    }
}

// ---------------------------------------------------------------------------
// combine the NCHUNK partials. 256 blocks x 128 threads.
// ---------------------------------------------------------------------------
__global__ __launch_bounds__(128) void combine_kernel(float* __restrict__ out)
{
    const int bh = blockIdx.x;            // b*NH + h
    const int d  = threadIdx.x;
    const int i0 = bh * NCHUNK;

    float gm = g_pm[i0];
#pragma unroll
    for (int c = 1; c < NCHUNK; ++c) gm = fmaxf(gm, g_pm[i0 + c]);

    float den = 0.f, num = 0.f;
#pragma unroll
    for (int c = 0; c < NCHUNK; ++c) {
        const float e = __expf(g_pm[i0 + c] - gm);
        den += e * g_ps[i0 + c];
        num += e * g_po[(size_t)(i0 + c) * HD + d];
    }
    out[(size_t)bh * HD + d] = num / den;
}

// ---------------------------------------------------------------------------
extern "C" void kernel_launch(void* const* d_in, const int* in_sizes, int n_in,
                              void* d_out, int out_size)
{
    const float* hs = (const float*)d_in[0];  // (8, 1536)
    const float* kv = (const float*)d_in[1];  // (8, 4096, 32, 256)
    const float* W  = (const float*)d_in[2];  // (1536, 4096)
    const float* bq = (const float*)d_in[3];  // (4096,)
    float* out = (float*)d_out;               // (8, 4096)

    qproj1_kernel<<<CB * RB, 256>>>(hs, W);
    qproj2_kernel<<<NQ / 128, 256>>>(bq);
    attn_kernel<<<BSZ * NH * NCHUNK, 256>>>(kv);
    combine_kernel<<<BSZ * NH, 128>>>(out);
}